// round 8
// baseline (speedup 1.0000x reference)
#include <cuda_runtime.h>
#include <cstdint>

#define N_NODES 50000
#define N_EDGES 800000
#define IN_CH   256
#define OUT_CH  64
#define HEADS   4
#define OUTF    (HEADS * OUT_CH)   // 256

// ---------------- device scratch (no allocs allowed) ----------------
__device__ __align__(16) float g_xh[(size_t)N_NODES * OUTF];    // projected features [N, 256]
__device__ __align__(16) float g_wcat[IN_CH * OUTF];            // fused weight [256][256]
__device__ __align__(16) float g_asrc[N_NODES * HEADS];         // [N, 4]
__device__ __align__(16) float g_adst[N_NODES * HEADS];         // [N, 4]
__device__ int g_cnt[N_NODES];                                  // per-row edge count
__device__ int g_off[N_NODES + 1];                              // CSR offsets
__device__ int g_cur[N_NODES];                                  // reorder cursors
__device__ int g_ecol[N_EDGES];                                 // CSR col per slot
__device__ __align__(16) float g_eexp[(size_t)N_EDGES * HEADS]; // CSR exp(logit) per slot

__device__ __forceinline__ int clamp_idx(int v) {
    return min(max(v, 0), N_NODES - 1);
}

// ---------------- init: zero row histogram ----------------
__global__ void k_init() {
    int i = blockIdx.x * blockDim.x + threadIdx.x;
    if (i < N_NODES) g_cnt[i] = 0;
}

// ---------------- weight reorder: W[h][f][c] -> Wcat[f][h*64+c] ----------------
__global__ void k_wrc(const float* __restrict__ w) {
    int i = blockIdx.x * blockDim.x + threadIdx.x;
    if (i >= HEADS * IN_CH * OUT_CH) return;
    int h = i >> 14;          // / (256*64)
    int f = (i >> 6) & 255;
    int c = i & 63;
    g_wcat[f * OUTF + h * OUT_CH + c] = w[i];
}

// ---------------- fused projection GEMM: x[50000,256] @ Wcat[256,256] -> g_xh ----------------
// 128x128x8 tiles, double-buffered smem, 256 threads, 8x8 microtile
__global__ void __launch_bounds__(256) k_gemm(const float* __restrict__ x) {
    constexpr int BM = 128, BN = 128, BK = 8;
    constexpr int NK = IN_CH / BK;   // 32
    __shared__ float As[2][BK][BM];  // 4 KB each
    __shared__ float Bs[2][BK][BN];

    const int tid = threadIdx.x;
    const int m0  = blockIdx.x * BM;
    const int n0  = blockIdx.y * BN;

    const int tx = tid & 15;    // N dir: cols tx*8..tx*8+7
    const int ty = tid >> 4;    // M dir: rows ty*8..ty*8+7

    // global-load assignments
    const int a_r = tid >> 1;          // 0..127
    const int a_c = (tid & 1) * 4;     // 0 or 4
    const int b_r = tid >> 6;          // 0..3  (x2 rows per thread? no: 8 rows,64 thr/row)
    // B tile is 8x128 = 256 float4: row = tid>>5 (0..7), col4 = (tid&31)
    const int bb_r = tid >> 5;
    const int bb_c = (tid & 31) * 4;
    (void)b_r;

    const bool a_ok = (m0 + a_r) < N_NODES;
    const float* a_ptr = x + (size_t)(m0 + a_r) * IN_CH + a_c;
    const float* b_ptr = g_wcat + (size_t)bb_r * OUTF + n0 + bb_c;

    float acc[8][8];
    #pragma unroll
    for (int i = 0; i < 8; i++)
        #pragma unroll
        for (int j = 0; j < 8; j++) acc[i][j] = 0.f;

    // preload tile 0
    {
        float4 va = a_ok ? *reinterpret_cast<const float4*>(a_ptr)
                         : make_float4(0.f, 0.f, 0.f, 0.f);
        As[0][a_c + 0][a_r] = va.x;
        As[0][a_c + 1][a_r] = va.y;
        As[0][a_c + 2][a_r] = va.z;
        As[0][a_c + 3][a_r] = va.w;
        float4 vb = *reinterpret_cast<const float4*>(b_ptr);
        *reinterpret_cast<float4*>(&Bs[0][bb_r][bb_c]) = vb;
    }
    __syncthreads();

    for (int t = 0; t < NK; t++) {
        const int buf = t & 1;
        float4 pa = make_float4(0.f, 0.f, 0.f, 0.f), pb;
        const bool more = (t + 1) < NK;
        if (more) {
            if (a_ok) pa = *reinterpret_cast<const float4*>(a_ptr + (t + 1) * BK);
            pb = *reinterpret_cast<const float4*>(b_ptr + (size_t)(t + 1) * BK * OUTF);
        }

        #pragma unroll
        for (int k = 0; k < BK; k++) {
            float a[8], b[8];
            *reinterpret_cast<float4*>(a)     = *reinterpret_cast<const float4*>(&As[buf][k][ty * 8]);
            *reinterpret_cast<float4*>(a + 4) = *reinterpret_cast<const float4*>(&As[buf][k][ty * 8 + 4]);
            *reinterpret_cast<float4*>(b)     = *reinterpret_cast<const float4*>(&Bs[buf][k][tx * 8]);
            *reinterpret_cast<float4*>(b + 4) = *reinterpret_cast<const float4*>(&Bs[buf][k][tx * 8 + 4]);
            #pragma unroll
            for (int i = 0; i < 8; i++)
                #pragma unroll
                for (int j = 0; j < 8; j++)
                    acc[i][j] = fmaf(a[i], b[j], acc[i][j]);
        }

        if (more) {
            const int nb = buf ^ 1;
            As[nb][a_c + 0][a_r] = pa.x;
            As[nb][a_c + 1][a_r] = pa.y;
            As[nb][a_c + 2][a_r] = pa.z;
            As[nb][a_c + 3][a_r] = pa.w;
            *reinterpret_cast<float4*>(&Bs[nb][bb_r][bb_c]) = pb;
        }
        __syncthreads();
    }

    #pragma unroll
    for (int i = 0; i < 8; i++) {
        int m = m0 + ty * 8 + i;
        if (m < N_NODES) {
            float* dst = g_xh + (size_t)m * OUTF + n0 + tx * 8;
            *reinterpret_cast<float4*>(dst)     = make_float4(acc[i][0], acc[i][1], acc[i][2], acc[i][3]);
            *reinterpret_cast<float4*>(dst + 4) = make_float4(acc[i][4], acc[i][5], acc[i][6], acc[i][7]);
        }
    }
}

// ---------------- attention logits per (node, head) ----------------
__global__ void k_alpha(const float* __restrict__ att_src, const float* __restrict__ att_dst) {
    int i = blockIdx.x * blockDim.x + threadIdx.x;
    if (i >= N_NODES * HEADS) return;
    int n = i >> 2, h = i & 3;
    const float4* xr = reinterpret_cast<const float4*>(g_xh) + (size_t)n * 64 + h * 16;
    const float4* sa = reinterpret_cast<const float4*>(att_src) + h * 16;
    const float4* da = reinterpret_cast<const float4*>(att_dst) + h * 16;
    float s = 0.f, d = 0.f;
    #pragma unroll
    for (int t = 0; t < 16; t++) {
        float4 v = xr[t];
        float4 a = sa[t];
        float4 b = da[t];
        s += v.x * a.x + v.y * a.y + v.z * a.z + v.w * a.w;
        d += v.x * b.x + v.y * b.y + v.z * b.z + v.w * b.w;
    }
    g_asrc[i] = s;
    g_adst[i] = d;
}

// ---------------- histogram of destination rows ----------------
__global__ void k_hist(const int* __restrict__ ei) {
    int e = blockIdx.x * blockDim.x + threadIdx.x;
    if (e >= N_EDGES) return;
    atomicAdd(&g_cnt[clamp_idx(ei[e])], 1);
}

// ---------------- exclusive scan over 50k counters (single block) ----------------
__global__ void k_scan() {
    constexpr int T = 1024;
    constexpr int CHUNK = (N_NODES + T - 1) / T;   // 49
    __shared__ int partial[T];
    int t = threadIdx.x;
    int beg = t * CHUNK;
    int end = min(beg + CHUNK, N_NODES);
    int s = 0;
    for (int i = beg; i < end; i++) s += g_cnt[i];
    partial[t] = s;
    __syncthreads();
    for (int d = 1; d < T; d <<= 1) {
        int v = partial[t];
        int add = (t >= d) ? partial[t - d] : 0;
        __syncthreads();
        partial[t] = v + add;
        __syncthreads();
    }
    int run = (t > 0) ? partial[t - 1] : 0;
    for (int i = beg; i < end; i++) {
        g_off[i] = run;
        g_cur[i] = run;
        run += g_cnt[i];
    }
    if (t == T - 1) g_off[N_NODES] = N_EDGES;
}

// ---------------- fused edge pass: logits -> exp, reorder into CSR slots ----------------
__global__ void k_edge_fused(const int* __restrict__ ei) {
    int e = blockIdx.x * blockDim.x + threadIdx.x;
    if (e >= N_EDGES) return;
    int row = clamp_idx(ei[e]);
    int col = clamp_idx(ei[N_EDGES + e]);
    float4 s = *reinterpret_cast<const float4*>(g_asrc + row * 4);
    float4 d = *reinterpret_cast<const float4*>(g_adst + col * 4);
    float a0 = s.x + d.x, a1 = s.y + d.y, a2 = s.z + d.z, a3 = s.w + d.w;
    a0 = a0 > 0.f ? a0 : 0.2f * a0;
    a1 = a1 > 0.f ? a1 : 0.2f * a1;
    a2 = a2 > 0.f ? a2 : 0.2f * a2;
    a3 = a3 > 0.f ? a3 : 0.2f * a3;
    float4 p = make_float4(__expf(a0), __expf(a1), __expf(a2), __expf(a3));
    int pos = atomicAdd(&g_cur[row], 1);
    g_ecol[pos] = col;
    *reinterpret_cast<float4*>(g_eexp + (size_t)pos * 4) = p;
}

// ---------------- CSR gather: one warp per destination node, single pass ----------------
__global__ void k_csr(const float* __restrict__ bias, float* __restrict__ out) {
    int warp = (blockIdx.x * blockDim.x + threadIdx.x) >> 5;
    if (warp >= N_NODES) return;
    int lane = threadIdx.x & 31;
    int n = warp;
    int off = g_off[n];
    int deg = g_off[n + 1] - off;

    // lane owns float4 slots lane and lane+32 of the 64-slot output row
    const int j0 = lane, j1 = lane + 32;
    const int h0 = j0 >> 4;        // 0 or 1
    const int h1 = j1 >> 4;        // 2 or 3
    float4 acc0 = make_float4(0.f, 0.f, 0.f, 0.f);
    float4 acc1 = make_float4(0.f, 0.f, 0.f, 0.f);
    float4 den  = make_float4(0.f, 0.f, 0.f, 0.f);   // every lane sees all edges

    for (int j = 0; j < deg; j++) {
        int idx = off + j;
        int c = g_ecol[idx];                                               // broadcast
        float4 p = *reinterpret_cast<const float4*>(g_eexp + (size_t)idx * 4); // broadcast
        den.x += p.x; den.y += p.y; den.z += p.z; den.w += p.w;
        float a0 = h0 ? p.y : p.x;
        float a1 = (h1 == 3) ? p.w : p.z;
        const float4* src = reinterpret_cast<const float4*>(g_xh) + (size_t)c * 64;
        float4 v = src[j0];
        float4 u = src[j1];
        acc0.x = fmaf(a0, v.x, acc0.x); acc0.y = fmaf(a0, v.y, acc0.y);
        acc0.z = fmaf(a0, v.z, acc0.z); acc0.w = fmaf(a0, v.w, acc0.w);
        acc1.x = fmaf(a1, u.x, acc1.x); acc1.y = fmaf(a1, u.y, acc1.y);
        acc1.z = fmaf(a1, u.z, acc1.z); acc1.w = fmaf(a1, u.w, acc1.w);
    }

    float r0 = 1.f / fmaxf(h0 ? den.y : den.x, 1e-16f);
    float r1 = 1.f / fmaxf((h1 == 3) ? den.w : den.z, 1e-16f);

    const float4* b4 = reinterpret_cast<const float4*>(bias);
    float4 b0 = b4[j0], b1 = b4[j1];
    acc0.x = fmaf(acc0.x, r0, b0.x); acc0.y = fmaf(acc0.y, r0, b0.y);
    acc0.z = fmaf(acc0.z, r0, b0.z); acc0.w = fmaf(acc0.w, r0, b0.w);
    acc1.x = fmaf(acc1.x, r1, b1.x); acc1.y = fmaf(acc1.y, r1, b1.y);
    acc1.z = fmaf(acc1.z, r1, b1.z); acc1.w = fmaf(acc1.w, r1, b1.w);
    float4* dst = reinterpret_cast<float4*>(out) + (size_t)n * 64;
    dst[j0] = acc0;
    dst[j1] = acc1;
}

// ---------------- launch ----------------
extern "C" void kernel_launch(void* const* d_in, const int* in_sizes, int n_in,
                              void* d_out, int out_size) {
    const float* x       = (const float*)d_in[0];
    const int*   ei      = (const int*)d_in[1];       // int32 (JAX x64 disabled)
    const float* w       = (const float*)d_in[2];
    const float* att_src = (const float*)d_in[3];
    const float* att_dst = (const float*)d_in[4];
    const float* bias    = (const float*)d_in[5];
    float*       out     = (float*)d_out;

    k_init<<<(N_NODES + 255) / 256, 256>>>();
    k_wrc<<<(HEADS * IN_CH * OUT_CH + 255) / 256, 256>>>(w);
    k_hist<<<(N_EDGES + 255) / 256, 256>>>(ei);
    k_scan<<<1, 1024>>>();

    dim3 gg((N_NODES + 127) / 128, OUTF / 128);
    k_gemm<<<gg, 256>>>(x);

    k_alpha<<<(N_NODES * HEADS + 255) / 256, 256>>>(att_src, att_dst);
    k_edge_fused<<<(N_EDGES + 255) / 256, 256>>>(ei);
    k_csr<<<(N_NODES * 32 + 255) / 256, 256>>>(bias, out);
}

// round 9
// speedup vs baseline: 1.3741x; 1.3741x over previous
#include <cuda_runtime.h>
#include <cstdint>

#define N_NODES 50000
#define N_EDGES 800000
#define IN_CH   256
#define OUT_CH  64
#define HEADS   4
#define OUTF    (HEADS * OUT_CH)   // 256

typedef unsigned long long u64;

// ---------------- device scratch (no allocs allowed) ----------------
__device__ __align__(16) float g_xh[(size_t)N_NODES * OUTF];    // projected features [N, 256]
__device__ __align__(16) float g_wcat[IN_CH * OUTF];            // fused weight [256][256]
__device__ __align__(16) float g_asrc[N_NODES * HEADS];         // [N, 4]
__device__ __align__(16) float g_adst[N_NODES * HEADS];         // [N, 4]
__device__ int g_cnt[N_NODES];                                  // per-row edge count
__device__ int g_off[N_NODES + 1];                              // CSR offsets
__device__ int g_cur[N_NODES];                                  // reorder cursors
__device__ int g_bsum[64];                                      // scan block partials
__device__ int g_bpre[64];                                      // scan block prefixes
__device__ int g_ecol[N_EDGES];                                 // CSR col per slot
__device__ __align__(16) float g_eexp[(size_t)N_EDGES * HEADS]; // CSR exp(logit) per slot

__device__ __forceinline__ int clamp_idx(int v) {
    return min(max(v, 0), N_NODES - 1);
}

// packed f32x2 helpers (Blackwell): d = a*b + d elementwise on packed pairs
__device__ __forceinline__ void fma2(u64& d, u64 a, u64 b) {
    asm("fma.rn.f32x2 %0, %1, %2, %0;" : "+l"(d) : "l"(a), "l"(b));
}
__device__ __forceinline__ u64 pack2(float lo, float hi) {
    u64 p;
    asm("mov.b64 %0, {%1, %2};" : "=l"(p) : "f"(lo), "f"(hi));
    return p;
}
__device__ __forceinline__ void unpack2(u64 p, float& lo, float& hi) {
    asm("mov.b64 {%0, %1}, %2;" : "=f"(lo), "=f"(hi) : "l"(p));
}

// ---------------- init: zero row histogram ----------------
__global__ void k_init() {
    int i = blockIdx.x * blockDim.x + threadIdx.x;
    if (i < N_NODES) g_cnt[i] = 0;
}

// ---------------- weight reorder: W[h][f][c] -> Wcat[f][h*64+c] ----------------
__global__ void k_wrc(const float* __restrict__ w) {
    int i = blockIdx.x * blockDim.x + threadIdx.x;
    if (i >= HEADS * IN_CH * OUT_CH) return;
    int h = i >> 14;
    int f = (i >> 6) & 255;
    int c = i & 63;
    g_wcat[f * OUTF + h * OUT_CH + c] = w[i];
}

// ---------------- fused projection GEMM with packed f32x2 FMA ----------------
// 128x128x8 tiles, double-buffered, 256 threads, 8x8 microtile (4 col-pairs)
__global__ void __launch_bounds__(256) k_gemm(const float* __restrict__ x) {
    constexpr int BM = 128, BN = 128, BK = 8;
    constexpr int NK = IN_CH / BK;   // 32
    constexpr int AP = BM + 4;       // padded A row (bank-conflict-free stores)
    __shared__ float As[2][BK][AP];
    __shared__ float Bs[2][BK][BN];

    const int tid = threadIdx.x;
    const int m0  = blockIdx.x * BM;
    const int n0  = blockIdx.y * BN;

    const int tx = tid & 15;    // N dir: col groups tx*4 and 64+tx*4 (stride-4: bank-clean)
    const int ty = tid >> 4;    // M dir: rows ty*8..ty*8+7

    // global-load assignments
    const int a_r = tid >> 1;          // 0..127
    const int a_c = (tid & 1) * 4;     // 0 or 4
    const int bb_r = tid >> 5;         // 0..7
    const int bb_c = (tid & 31) * 4;   // 0..124

    const bool a_ok = (m0 + a_r) < N_NODES;
    const float* a_ptr = x + (size_t)(m0 + a_r) * IN_CH + a_c;
    const float* b_ptr = g_wcat + (size_t)bb_r * OUTF + n0 + bb_c;

    u64 acc2[8][4];
    #pragma unroll
    for (int i = 0; i < 8; i++)
        #pragma unroll
        for (int j = 0; j < 4; j++) acc2[i][j] = 0ull;

    // preload tile 0
    {
        float4 va = a_ok ? *reinterpret_cast<const float4*>(a_ptr)
                         : make_float4(0.f, 0.f, 0.f, 0.f);
        As[0][a_c + 0][a_r] = va.x;
        As[0][a_c + 1][a_r] = va.y;
        As[0][a_c + 2][a_r] = va.z;
        As[0][a_c + 3][a_r] = va.w;
        float4 vb = *reinterpret_cast<const float4*>(b_ptr);
        *reinterpret_cast<float4*>(&Bs[0][bb_r][bb_c]) = vb;
    }
    __syncthreads();

    for (int t = 0; t < NK; t++) {
        const int buf = t & 1;
        float4 pa = make_float4(0.f, 0.f, 0.f, 0.f), pb;
        const bool more = (t + 1) < NK;
        if (more) {
            if (a_ok) pa = *reinterpret_cast<const float4*>(a_ptr + (t + 1) * BK);
            pb = *reinterpret_cast<const float4*>(b_ptr + (size_t)(t + 1) * BK * OUTF);
        }

        #pragma unroll
        for (int k = 0; k < BK; k++) {
            float4 va0 = *reinterpret_cast<const float4*>(&As[buf][k][ty * 8]);
            float4 va1 = *reinterpret_cast<const float4*>(&As[buf][k][ty * 8 + 4]);
            float4 vb0 = *reinterpret_cast<const float4*>(&Bs[buf][k][tx * 4]);
            float4 vb1 = *reinterpret_cast<const float4*>(&Bs[buf][k][64 + tx * 4]);
            u64 B0 = pack2(vb0.x, vb0.y);
            u64 B1 = pack2(vb0.z, vb0.w);
            u64 B2 = pack2(vb1.x, vb1.y);
            u64 B3 = pack2(vb1.z, vb1.w);
            float av[8] = {va0.x, va0.y, va0.z, va0.w, va1.x, va1.y, va1.z, va1.w};
            #pragma unroll
            for (int i = 0; i < 8; i++) {
                u64 A = pack2(av[i], av[i]);
                fma2(acc2[i][0], A, B0);
                fma2(acc2[i][1], A, B1);
                fma2(acc2[i][2], A, B2);
                fma2(acc2[i][3], A, B3);
            }
        }

        if (more) {
            const int nb = buf ^ 1;
            As[nb][a_c + 0][a_r] = pa.x;
            As[nb][a_c + 1][a_r] = pa.y;
            As[nb][a_c + 2][a_r] = pa.z;
            As[nb][a_c + 3][a_r] = pa.w;
            *reinterpret_cast<float4*>(&Bs[nb][bb_r][bb_c]) = pb;
        }
        __syncthreads();
    }

    #pragma unroll
    for (int i = 0; i < 8; i++) {
        int m = m0 + ty * 8 + i;
        if (m < N_NODES) {
            float4 o0, o1;
            unpack2(acc2[i][0], o0.x, o0.y);
            unpack2(acc2[i][1], o0.z, o0.w);
            unpack2(acc2[i][2], o1.x, o1.y);
            unpack2(acc2[i][3], o1.z, o1.w);
            float* dst = g_xh + (size_t)m * OUTF + n0;
            *reinterpret_cast<float4*>(dst + tx * 4)      = o0;
            *reinterpret_cast<float4*>(dst + 64 + tx * 4) = o1;
        }
    }
}

// ---------------- attention logits per (node, head) ----------------
__global__ void k_alpha(const float* __restrict__ att_src, const float* __restrict__ att_dst) {
    int i = blockIdx.x * blockDim.x + threadIdx.x;
    if (i >= N_NODES * HEADS) return;
    int n = i >> 2, h = i & 3;
    const float4* xr = reinterpret_cast<const float4*>(g_xh) + (size_t)n * 64 + h * 16;
    const float4* sa = reinterpret_cast<const float4*>(att_src) + h * 16;
    const float4* da = reinterpret_cast<const float4*>(att_dst) + h * 16;
    float s = 0.f, d = 0.f;
    #pragma unroll
    for (int t = 0; t < 16; t++) {
        float4 v = xr[t];
        float4 a = sa[t];
        float4 b = da[t];
        s += v.x * a.x + v.y * a.y + v.z * a.z + v.w * a.w;
        d += v.x * b.x + v.y * b.y + v.z * b.z + v.w * b.w;
    }
    g_asrc[i] = s;
    g_adst[i] = d;
}

// ---------------- histogram of destination rows ----------------
__global__ void k_hist(const int* __restrict__ ei) {
    int e = blockIdx.x * blockDim.x + threadIdx.x;
    if (e >= N_EDGES) return;
    atomicAdd(&g_cnt[clamp_idx(ei[e])], 1);
}

// ---------------- parallel scan, phase 1: per-block sums (49 blocks x 1024) ----------------
__global__ void k_scan1() {
    __shared__ int wsum[32];
    int t = threadIdx.x;
    int i = blockIdx.x * 1024 + t;
    int v = (i < N_NODES) ? g_cnt[i] : 0;
    int lane = t & 31, wid = t >> 5;
    #pragma unroll
    for (int d = 16; d > 0; d >>= 1) v += __shfl_xor_sync(0xffffffffu, v, d);
    if (lane == 0) wsum[wid] = v;
    __syncthreads();
    if (wid == 0) {
        int s = wsum[lane];
        #pragma unroll
        for (int d = 16; d > 0; d >>= 1) s += __shfl_xor_sync(0xffffffffu, s, d);
        if (lane == 0) g_bsum[blockIdx.x] = s;
    }
}

// ---------------- phase 2: exclusive scan of 49 partials (tiny) ----------------
__global__ void k_scan2(int nblk) {
    __shared__ int sm[64];
    int t = threadIdx.x;
    if (t < nblk) sm[t] = g_bsum[t];
    __syncthreads();
    if (t == 0) {
        int run = 0;
        for (int i = 0; i < nblk; i++) { int c = sm[i]; sm[i] = run; run += c; }
    }
    __syncthreads();
    if (t < nblk) g_bpre[t] = sm[t];
}

// ---------------- phase 3: block-local exclusive scan + prefix -> offsets ----------------
__global__ void k_scan3() {
    __shared__ int wsum[32];
    int t = threadIdx.x;
    int i = blockIdx.x * 1024 + t;
    int v = (i < N_NODES) ? g_cnt[i] : 0;
    int lane = t & 31, wid = t >> 5;
    // warp inclusive scan
    int inc = v;
    #pragma unroll
    for (int d = 1; d < 32; d <<= 1) {
        int n = __shfl_up_sync(0xffffffffu, inc, d);
        if (lane >= d) inc += n;
    }
    if (lane == 31) wsum[wid] = inc;
    __syncthreads();
    if (wid == 0) {
        int s = wsum[lane];
        #pragma unroll
        for (int d = 1; d < 32; d <<= 1) {
            int n = __shfl_up_sync(0xffffffffu, s, d);
            if (lane >= d) s += n;
        }
        wsum[lane] = s;
    }
    __syncthreads();
    int ex = inc - v + ((wid > 0) ? wsum[wid - 1] : 0);
    int off = g_bpre[blockIdx.x] + ex;
    if (i < N_NODES) { g_off[i] = off; g_cur[i] = off; }
    if (blockIdx.x == 0 && t == 0) g_off[N_NODES] = N_EDGES;
}

// ---------------- fused edge pass: logits -> exp, reorder into CSR slots ----------------
__global__ void k_edge_fused(const int* __restrict__ ei) {
    int e = blockIdx.x * blockDim.x + threadIdx.x;
    if (e >= N_EDGES) return;
    int row = clamp_idx(ei[e]);
    int col = clamp_idx(ei[N_EDGES + e]);
    float4 s = *reinterpret_cast<const float4*>(g_asrc + row * 4);
    float4 d = *reinterpret_cast<const float4*>(g_adst + col * 4);
    float a0 = s.x + d.x, a1 = s.y + d.y, a2 = s.z + d.z, a3 = s.w + d.w;
    a0 = a0 > 0.f ? a0 : 0.2f * a0;
    a1 = a1 > 0.f ? a1 : 0.2f * a1;
    a2 = a2 > 0.f ? a2 : 0.2f * a2;
    a3 = a3 > 0.f ? a3 : 0.2f * a3;
    float4 p = make_float4(__expf(a0), __expf(a1), __expf(a2), __expf(a3));
    int pos = atomicAdd(&g_cur[row], 1);
    g_ecol[pos] = col;
    *reinterpret_cast<float4*>(g_eexp + (size_t)pos * 4) = p;
}

// ---------------- CSR gather: one warp per destination node, single pass ----------------
__global__ void k_csr(const float* __restrict__ bias, float* __restrict__ out) {
    int warp = (blockIdx.x * blockDim.x + threadIdx.x) >> 5;
    if (warp >= N_NODES) return;
    int lane = threadIdx.x & 31;
    int n = warp;
    int off = g_off[n];
    int deg = g_off[n + 1] - off;

    const int j0 = lane, j1 = lane + 32;
    const int h0 = j0 >> 4;        // 0 or 1
    const int h1 = j1 >> 4;        // 2 or 3
    float4 acc0 = make_float4(0.f, 0.f, 0.f, 0.f);
    float4 acc1 = make_float4(0.f, 0.f, 0.f, 0.f);
    float4 den  = make_float4(0.f, 0.f, 0.f, 0.f);

    for (int j = 0; j < deg; j++) {
        int idx = off + j;
        int c = g_ecol[idx];                                               // broadcast
        float4 p = *reinterpret_cast<const float4*>(g_eexp + (size_t)idx * 4); // broadcast
        den.x += p.x; den.y += p.y; den.z += p.z; den.w += p.w;
        float a0 = h0 ? p.y : p.x;
        float a1 = (h1 == 3) ? p.w : p.z;
        const float4* src = reinterpret_cast<const float4*>(g_xh) + (size_t)c * 64;
        float4 v = src[j0];
        float4 u = src[j1];
        acc0.x = fmaf(a0, v.x, acc0.x); acc0.y = fmaf(a0, v.y, acc0.y);
        acc0.z = fmaf(a0, v.z, acc0.z); acc0.w = fmaf(a0, v.w, acc0.w);
        acc1.x = fmaf(a1, u.x, acc1.x); acc1.y = fmaf(a1, u.y, acc1.y);
        acc1.z = fmaf(a1, u.z, acc1.z); acc1.w = fmaf(a1, u.w, acc1.w);
    }

    float r0 = 1.f / fmaxf(h0 ? den.y : den.x, 1e-16f);
    float r1 = 1.f / fmaxf((h1 == 3) ? den.w : den.z, 1e-16f);

    const float4* b4 = reinterpret_cast<const float4*>(bias);
    float4 b0 = b4[j0], b1 = b4[j1];
    acc0.x = fmaf(acc0.x, r0, b0.x); acc0.y = fmaf(acc0.y, r0, b0.y);
    acc0.z = fmaf(acc0.z, r0, b0.z); acc0.w = fmaf(acc0.w, r0, b0.w);
    acc1.x = fmaf(acc1.x, r1, b1.x); acc1.y = fmaf(acc1.y, r1, b1.y);
    acc1.z = fmaf(acc1.z, r1, b1.z); acc1.w = fmaf(acc1.w, r1, b1.w);
    float4* dst = reinterpret_cast<float4*>(out) + (size_t)n * 64;
    dst[j0] = acc0;
    dst[j1] = acc1;
}

// ---------------- launch ----------------
extern "C" void kernel_launch(void* const* d_in, const int* in_sizes, int n_in,
                              void* d_out, int out_size) {
    const float* x       = (const float*)d_in[0];
    const int*   ei      = (const int*)d_in[1];       // int32 (JAX x64 disabled)
    const float* w       = (const float*)d_in[2];
    const float* att_src = (const float*)d_in[3];
    const float* att_dst = (const float*)d_in[4];
    const float* bias    = (const float*)d_in[5];
    float*       out     = (float*)d_out;

    const int SCAN_BLOCKS = (N_NODES + 1023) / 1024;   // 49

    k_init<<<(N_NODES + 255) / 256, 256>>>();
    k_wrc<<<(HEADS * IN_CH * OUT_CH + 255) / 256, 256>>>(w);
    k_hist<<<(N_EDGES + 255) / 256, 256>>>(ei);
    k_scan1<<<SCAN_BLOCKS, 1024>>>();
    k_scan2<<<1, 64>>>(SCAN_BLOCKS);
    k_scan3<<<SCAN_BLOCKS, 1024>>>();

    dim3 gg((N_NODES + 127) / 128, OUTF / 128);
    k_gemm<<<gg, 256>>>(x);

    k_alpha<<<(N_NODES * HEADS + 255) / 256, 256>>>(att_src, att_dst);
    k_edge_fused<<<(N_EDGES + 255) / 256, 256>>>(ei);
    k_csr<<<(N_NODES * 32 + 255) / 256, 256>>>(bias, out);
}

// round 10
// speedup vs baseline: 1.8903x; 1.3756x over previous
#include <cuda_runtime.h>
#include <cstdint>

#define N_NODES 50000
#define N_EDGES 800000
#define IN_CH   256
#define OUT_CH  64
#define HEADS   4
#define OUTF    (HEADS * OUT_CH)   // 256

// ---------------- device scratch (no allocs allowed) ----------------
__device__ __align__(16) float g_xh[(size_t)N_NODES * OUTF];    // projected features [N, 256]
__device__ __align__(16) float g_wcat[IN_CH * OUTF];            // fused weight [256][256]
__device__ __align__(16) float g_asrc[N_NODES * HEADS];         // [N, 4]
__device__ __align__(16) float g_adst[N_NODES * HEADS];         // [N, 4]
__device__ int g_cnt[N_NODES];                                  // per-row edge count
__device__ int g_off[N_NODES + 1];                              // CSR offsets
__device__ int g_cur[N_NODES];                                  // reorder cursors
__device__ int g_bsum[64];                                      // scan block partials
__device__ int g_bpre[64];                                      // scan block prefixes
__device__ int g_ecol[N_EDGES];                                 // CSR col per slot
__device__ __align__(16) float g_eexp[(size_t)N_EDGES * HEADS]; // CSR exp(logit) per slot

__device__ __forceinline__ int clamp_idx(int v) {
    return min(max(v, 0), N_NODES - 1);
}

__device__ __forceinline__ uint32_t f2tf32(float f) {
    uint32_t u;
    asm("cvt.rna.tf32.f32 %0, %1;" : "=r"(u) : "f"(f));
    return u;
}

__device__ __forceinline__ void mma_tf32(float* c, const uint32_t* a, uint32_t b0, uint32_t b1) {
    asm("mma.sync.aligned.m16n8k8.row.col.f32.tf32.tf32.f32 "
        "{%0,%1,%2,%3}, {%4,%5,%6,%7}, {%8,%9}, {%0,%1,%2,%3};"
        : "+f"(c[0]), "+f"(c[1]), "+f"(c[2]), "+f"(c[3])
        : "r"(a[0]), "r"(a[1]), "r"(a[2]), "r"(a[3]), "r"(b0), "r"(b1));
}

// ---------------- init: zero row histogram ----------------
__global__ void k_init() {
    int i = blockIdx.x * blockDim.x + threadIdx.x;
    if (i < N_NODES) g_cnt[i] = 0;
}

// ---------------- weight reorder: W[h][f][c] -> Wcat[f][h*64+c] ----------------
__global__ void k_wrc(const float* __restrict__ w) {
    int i = blockIdx.x * blockDim.x + threadIdx.x;
    if (i >= HEADS * IN_CH * OUT_CH) return;
    int h = i >> 14;
    int f = (i >> 6) & 255;
    int c = i & 63;
    g_wcat[f * OUTF + h * OUT_CH + c] = w[i];
}

// ---------------- projection GEMM: TF32 mma.sync, 128x128 block, 8 warps ----------------
// warp (wm, wn) = (wid&3, wid>>2) computes rows wm*32..+32, cols wn*64..+64
// per warp: 2 (m16) x 8 (n8) tiles, K in 16 chunks of BK=16 (2 k8-steps each)
__global__ void __launch_bounds__(256) k_gemm(const float* __restrict__ x) {
    constexpr int BM = 128, BK = 16;
    constexpr int NCK = IN_CH / BK;        // 16
    constexpr int ASTR = 20;               // A smem row stride (words)
    constexpr int BSTR = 136;              // B smem row stride (words)
    __shared__ uint32_t As[2][BM][ASTR];   // tf32 bits, [row][k]
    __shared__ uint32_t Bs[2][BK][BSTR];   // tf32 bits, [k][n]

    const int tid  = threadIdx.x;
    const int lane = tid & 31;
    const int wid  = tid >> 5;
    const int wm   = wid & 3;
    const int wn   = wid >> 2;
    const int m0   = blockIdx.x * BM;
    const int n0   = blockIdx.y * 128;

    // global-load assignments (per t in 0..1):
    //   A: idx = t*256+tid -> row=idx>>2 (0..127), col=(idx&3)*4
    //   B: idx = t*256+tid -> row=idx>>5 (0..15),  col=(idx&31)*4
    const int ar = tid >> 2, ac = (tid & 3) * 4;
    const int br = tid >> 5, bc = (tid & 31) * 4;

    float c[2][8][4];
    #pragma unroll
    for (int mt = 0; mt < 2; mt++)
        #pragma unroll
        for (int nt = 0; nt < 8; nt++)
            #pragma unroll
            for (int i = 0; i < 4; i++) c[mt][nt][i] = 0.f;

    auto load_chunk = [&](int ck, int buf) {
        #pragma unroll
        for (int t = 0; t < 2; t++) {
            int row = ar + t * 64;
            float4 v = make_float4(0.f, 0.f, 0.f, 0.f);
            if (m0 + row < N_NODES)
                v = *reinterpret_cast<const float4*>(x + (size_t)(m0 + row) * IN_CH + ck * BK + ac);
            uint4 u = make_uint4(f2tf32(v.x), f2tf32(v.y), f2tf32(v.z), f2tf32(v.w));
            *reinterpret_cast<uint4*>(&As[buf][row][ac]) = u;
        }
        #pragma unroll
        for (int t = 0; t < 2; t++) {
            int row = br + t * 8;
            float4 v = *reinterpret_cast<const float4*>(
                g_wcat + (size_t)(ck * BK + row) * OUTF + n0 + bc);
            uint4 u = make_uint4(f2tf32(v.x), f2tf32(v.y), f2tf32(v.z), f2tf32(v.w));
            *reinterpret_cast<uint4*>(&Bs[buf][row][bc]) = u;
        }
    };

    load_chunk(0, 0);
    __syncthreads();

    const int g  = lane >> 2;   // group id 0..7
    const int tg = lane & 3;    // thread in group 0..3

    for (int ck = 0; ck < NCK; ck++) {
        const int buf = ck & 1;

        #pragma unroll
        for (int ks = 0; ks < 2; ks++) {
            const int k0 = ks * 8;
            uint32_t a[2][4];
            #pragma unroll
            for (int mt = 0; mt < 2; mt++) {
                int r = wm * 32 + mt * 16 + g;
                a[mt][0] = As[buf][r][k0 + tg];
                a[mt][1] = As[buf][r + 8][k0 + tg];
                a[mt][2] = As[buf][r][k0 + tg + 4];
                a[mt][3] = As[buf][r + 8][k0 + tg + 4];
            }
            #pragma unroll
            for (int nt = 0; nt < 8; nt++) {
                int n = wn * 64 + nt * 8 + g;
                uint32_t b0 = Bs[buf][k0 + tg][n];
                uint32_t b1 = Bs[buf][k0 + tg + 4][n];
                mma_tf32(c[0][nt], a[0], b0, b1);
                mma_tf32(c[1][nt], a[1], b0, b1);
            }
        }

        if (ck + 1 < NCK) load_chunk(ck + 1, buf ^ 1);
        __syncthreads();
    }

    // epilogue: c0,c1 -> (row, 2*tg), c2,c3 -> (row+8, 2*tg)
    #pragma unroll
    for (int mt = 0; mt < 2; mt++) {
        int mA = m0 + wm * 32 + mt * 16 + g;
        #pragma unroll
        for (int nt = 0; nt < 8; nt++) {
            int n = n0 + wn * 64 + nt * 8 + tg * 2;
            if (mA < N_NODES)
                *reinterpret_cast<float2*>(g_xh + (size_t)mA * OUTF + n)
                    = make_float2(c[mt][nt][0], c[mt][nt][1]);
            if (mA + 8 < N_NODES)
                *reinterpret_cast<float2*>(g_xh + (size_t)(mA + 8) * OUTF + n)
                    = make_float2(c[mt][nt][2], c[mt][nt][3]);
        }
    }
}

// ---------------- attention logits per (node, head) ----------------
__global__ void k_alpha(const float* __restrict__ att_src, const float* __restrict__ att_dst) {
    int i = blockIdx.x * blockDim.x + threadIdx.x;
    if (i >= N_NODES * HEADS) return;
    int n = i >> 2, h = i & 3;
    const float4* xr = reinterpret_cast<const float4*>(g_xh) + (size_t)n * 64 + h * 16;
    const float4* sa = reinterpret_cast<const float4*>(att_src) + h * 16;
    const float4* da = reinterpret_cast<const float4*>(att_dst) + h * 16;
    float s = 0.f, d = 0.f;
    #pragma unroll
    for (int t = 0; t < 16; t++) {
        float4 v = xr[t];
        float4 a = sa[t];
        float4 b = da[t];
        s += v.x * a.x + v.y * a.y + v.z * a.z + v.w * a.w;
        d += v.x * b.x + v.y * b.y + v.z * b.z + v.w * b.w;
    }
    g_asrc[i] = s;
    g_adst[i] = d;
}

// ---------------- histogram of destination rows ----------------
__global__ void k_hist(const int* __restrict__ ei) {
    int e = blockIdx.x * blockDim.x + threadIdx.x;
    if (e >= N_EDGES) return;
    atomicAdd(&g_cnt[clamp_idx(ei[e])], 1);
}

// ---------------- parallel scan, phase 1: per-block sums ----------------
__global__ void k_scan1() {
    __shared__ int wsum[32];
    int t = threadIdx.x;
    int i = blockIdx.x * 1024 + t;
    int v = (i < N_NODES) ? g_cnt[i] : 0;
    int lane = t & 31, wid = t >> 5;
    #pragma unroll
    for (int d = 16; d > 0; d >>= 1) v += __shfl_xor_sync(0xffffffffu, v, d);
    if (lane == 0) wsum[wid] = v;
    __syncthreads();
    if (wid == 0) {
        int s = wsum[lane];
        #pragma unroll
        for (int d = 16; d > 0; d >>= 1) s += __shfl_xor_sync(0xffffffffu, s, d);
        if (lane == 0) g_bsum[blockIdx.x] = s;
    }
}

// ---------------- phase 2: exclusive scan of block partials ----------------
__global__ void k_scan2(int nblk) {
    __shared__ int sm[64];
    int t = threadIdx.x;
    if (t < nblk) sm[t] = g_bsum[t];
    __syncthreads();
    if (t == 0) {
        int run = 0;
        for (int i = 0; i < nblk; i++) { int c = sm[i]; sm[i] = run; run += c; }
    }
    __syncthreads();
    if (t < nblk) g_bpre[t] = sm[t];
}

// ---------------- phase 3: block-local exclusive scan + prefix -> offsets ----------------
__global__ void k_scan3() {
    __shared__ int wsum[32];
    int t = threadIdx.x;
    int i = blockIdx.x * 1024 + t;
    int v = (i < N_NODES) ? g_cnt[i] : 0;
    int lane = t & 31, wid = t >> 5;
    int inc = v;
    #pragma unroll
    for (int d = 1; d < 32; d <<= 1) {
        int n = __shfl_up_sync(0xffffffffu, inc, d);
        if (lane >= d) inc += n;
    }
    if (lane == 31) wsum[wid] = inc;
    __syncthreads();
    if (wid == 0) {
        int s = wsum[lane];
        #pragma unroll
        for (int d = 1; d < 32; d <<= 1) {
            int n = __shfl_up_sync(0xffffffffu, s, d);
            if (lane >= d) s += n;
        }
        wsum[lane] = s;
    }
    __syncthreads();
    int ex = inc - v + ((wid > 0) ? wsum[wid - 1] : 0);
    int off = g_bpre[blockIdx.x] + ex;
    if (i < N_NODES) { g_off[i] = off; g_cur[i] = off; }
    if (blockIdx.x == 0 && t == 0) g_off[N_NODES] = N_EDGES;
}

// ---------------- fused edge pass: logits -> exp, reorder into CSR slots ----------------
__global__ void k_edge_fused(const int* __restrict__ ei) {
    int e = blockIdx.x * blockDim.x + threadIdx.x;
    if (e >= N_EDGES) return;
    int row = clamp_idx(ei[e]);
    int col = clamp_idx(ei[N_EDGES + e]);
    float4 s = *reinterpret_cast<const float4*>(g_asrc + row * 4);
    float4 d = *reinterpret_cast<const float4*>(g_adst + col * 4);
    float a0 = s.x + d.x, a1 = s.y + d.y, a2 = s.z + d.z, a3 = s.w + d.w;
    a0 = a0 > 0.f ? a0 : 0.2f * a0;
    a1 = a1 > 0.f ? a1 : 0.2f * a1;
    a2 = a2 > 0.f ? a2 : 0.2f * a2;
    a3 = a3 > 0.f ? a3 : 0.2f * a3;
    float4 p = make_float4(__expf(a0), __expf(a1), __expf(a2), __expf(a3));
    int pos = atomicAdd(&g_cur[row], 1);
    g_ecol[pos] = col;
    *reinterpret_cast<float4*>(g_eexp + (size_t)pos * 4) = p;
}

// ---------------- CSR gather: one warp per destination node, single pass ----------------
__global__ void k_csr(const float* __restrict__ bias, float* __restrict__ out) {
    int warp = (blockIdx.x * blockDim.x + threadIdx.x) >> 5;
    if (warp >= N_NODES) return;
    int lane = threadIdx.x & 31;
    int n = warp;
    int off = g_off[n];
    int deg = g_off[n + 1] - off;

    const int j0 = lane, j1 = lane + 32;
    const int h0 = j0 >> 4;        // 0 or 1
    const int h1 = j1 >> 4;        // 2 or 3
    float4 acc0 = make_float4(0.f, 0.f, 0.f, 0.f);
    float4 acc1 = make_float4(0.f, 0.f, 0.f, 0.f);
    float4 den  = make_float4(0.f, 0.f, 0.f, 0.f);

    for (int j = 0; j < deg; j++) {
        int idx = off + j;
        int c = g_ecol[idx];                                               // broadcast
        float4 p = *reinterpret_cast<const float4*>(g_eexp + (size_t)idx * 4); // broadcast
        den.x += p.x; den.y += p.y; den.z += p.z; den.w += p.w;
        float a0 = h0 ? p.y : p.x;
        float a1 = (h1 == 3) ? p.w : p.z;
        const float4* src = reinterpret_cast<const float4*>(g_xh) + (size_t)c * 64;
        float4 v = src[j0];
        float4 u = src[j1];
        acc0.x = fmaf(a0, v.x, acc0.x); acc0.y = fmaf(a0, v.y, acc0.y);
        acc0.z = fmaf(a0, v.z, acc0.z); acc0.w = fmaf(a0, v.w, acc0.w);
        acc1.x = fmaf(a1, u.x, acc1.x); acc1.y = fmaf(a1, u.y, acc1.y);
        acc1.z = fmaf(a1, u.z, acc1.z); acc1.w = fmaf(a1, u.w, acc1.w);
    }

    float r0 = 1.f / fmaxf(h0 ? den.y : den.x, 1e-16f);
    float r1 = 1.f / fmaxf((h1 == 3) ? den.w : den.z, 1e-16f);

    const float4* b4 = reinterpret_cast<const float4*>(bias);
    float4 b0 = b4[j0], b1 = b4[j1];
    acc0.x = fmaf(acc0.x, r0, b0.x); acc0.y = fmaf(acc0.y, r0, b0.y);
    acc0.z = fmaf(acc0.z, r0, b0.z); acc0.w = fmaf(acc0.w, r0, b0.w);
    acc1.x = fmaf(acc1.x, r1, b1.x); acc1.y = fmaf(acc1.y, r1, b1.y);
    acc1.z = fmaf(acc1.z, r1, b1.z); acc1.w = fmaf(acc1.w, r1, b1.w);
    float4* dst = reinterpret_cast<float4*>(out) + (size_t)n * 64;
    dst[j0] = acc0;
    dst[j1] = acc1;
}

// ---------------- launch ----------------
extern "C" void kernel_launch(void* const* d_in, const int* in_sizes, int n_in,
                              void* d_out, int out_size) {
    const float* x       = (const float*)d_in[0];
    const int*   ei      = (const int*)d_in[1];       // int32 (JAX x64 disabled)
    const float* w       = (const float*)d_in[2];
    const float* att_src = (const float*)d_in[3];
    const float* att_dst = (const float*)d_in[4];
    const float* bias    = (const float*)d_in[5];
    float*       out     = (float*)d_out;

    const int SCAN_BLOCKS = (N_NODES + 1023) / 1024;   // 49

    k_init<<<(N_NODES + 255) / 256, 256>>>();
    k_wrc<<<(HEADS * IN_CH * OUT_CH + 255) / 256, 256>>>(w);
    k_hist<<<(N_EDGES + 255) / 256, 256>>>(ei);
    k_scan1<<<SCAN_BLOCKS, 1024>>>();
    k_scan2<<<1, 64>>>(SCAN_BLOCKS);
    k_scan3<<<SCAN_BLOCKS, 1024>>>();

    dim3 gg((N_NODES + 127) / 128, OUTF / 128);
    k_gemm<<<gg, 256>>>(x);

    k_alpha<<<(N_NODES * HEADS + 255) / 256, 256>>>(att_src, att_dst);
    k_edge_fused<<<(N_EDGES + 255) / 256, 256>>>(ei);
    k_csr<<<(N_NODES * 32 + 255) / 256, 256>>>(bias, out);
}

// round 12
// speedup vs baseline: 2.1953x; 1.1613x over previous
#include <cuda_runtime.h>
#include <cuda_fp16.h>
#include <cstdint>

#define N_NODES 50000
#define N_EDGES 800000
#define IN_CH   256
#define OUT_CH  64
#define HEADS   4
#define OUTF    (HEADS * OUT_CH)   // 256

// ---------------- device scratch (no allocs allowed) ----------------
__device__ __align__(16) __half g_xhh[(size_t)N_NODES * OUTF];  // projected features, fp16
__device__ __align__(16) float g_wcat[IN_CH * OUTF];            // fused weight [256][256]
__device__ __align__(16) float g_asrc[N_NODES * HEADS];         // [N, 4]
__device__ __align__(16) float g_adst[N_NODES * HEADS];         // [N, 4]
__device__ int g_cnt[N_NODES];                                  // per-row edge count
__device__ int g_off[N_NODES + 1];                              // CSR offsets
__device__ int g_cur[N_NODES];                                  // reorder cursors
__device__ int g_bsum[64];                                      // scan block partials
__device__ int g_bpre[64];                                      // scan block prefixes
__device__ int g_ecol[N_EDGES];                                 // CSR col per slot
__device__ __align__(16) float g_eexp[(size_t)N_EDGES * HEADS]; // CSR exp(logit) per slot

__device__ __forceinline__ int clamp_idx(int v) {
    return min(max(v, 0), N_NODES - 1);
}

__device__ __forceinline__ uint32_t f2tf32(float f) {
    uint32_t u;
    asm("cvt.rna.tf32.f32 %0, %1;" : "=r"(u) : "f"(f));
    return u;
}

__device__ __forceinline__ void mma_tf32(float* c, const uint32_t* a, uint32_t b0, uint32_t b1) {
    asm("mma.sync.aligned.m16n8k8.row.col.f32.tf32.tf32.f32 "
        "{%0,%1,%2,%3}, {%4,%5,%6,%7}, {%8,%9}, {%0,%1,%2,%3};"
        : "+f"(c[0]), "+f"(c[1]), "+f"(c[2]), "+f"(c[3])
        : "r"(a[0]), "r"(a[1]), "r"(a[2]), "r"(a[3]), "r"(b0), "r"(b1));
}

// ---------------- init: zero row histogram ----------------
__global__ void k_init() {
    int i = blockIdx.x * blockDim.x + threadIdx.x;
    if (i < N_NODES) g_cnt[i] = 0;
}

// ---------------- weight reorder: W[h][f][c] -> Wcat[f][h*64+c] ----------------
__global__ void k_wrc(const float* __restrict__ w) {
    int i = blockIdx.x * blockDim.x + threadIdx.x;
    if (i >= HEADS * IN_CH * OUT_CH) return;
    int h = i >> 14;
    int f = (i >> 6) & 255;
    int c = i & 63;
    g_wcat[f * OUTF + h * OUT_CH + c] = w[i];
}

// ---------------- projection GEMM: TF32 mma.sync + fused alpha + fp16 epilogue ----------------
// warp (wm, wn): rows wm*32..+32, cols wn*64..+64 (= exactly one head)
__global__ void __launch_bounds__(256) k_gemm(const float* __restrict__ x,
                                              const float* __restrict__ att_src,
                                              const float* __restrict__ att_dst) {
    constexpr int BM = 128, BK = 16;
    constexpr int NCK = IN_CH / BK;        // 16
    constexpr int ASTR = 20;
    constexpr int BSTR = 136;
    __shared__ uint32_t As[2][BM][ASTR];
    __shared__ uint32_t Bs[2][BK][BSTR];

    const int tid  = threadIdx.x;
    const int lane = tid & 31;
    const int wid  = tid >> 5;
    const int wm   = wid & 3;
    const int wn   = wid >> 2;
    const int m0   = blockIdx.x * BM;
    const int n0   = blockIdx.y * 128;

    const int ar = tid >> 2, ac = (tid & 3) * 4;
    const int br = tid >> 5, bc = (tid & 31) * 4;

    float c[2][8][4];
    #pragma unroll
    for (int mt = 0; mt < 2; mt++)
        #pragma unroll
        for (int nt = 0; nt < 8; nt++)
            #pragma unroll
            for (int i = 0; i < 4; i++) c[mt][nt][i] = 0.f;

    auto load_chunk = [&](int ck, int buf) {
        #pragma unroll
        for (int t = 0; t < 2; t++) {
            int row = ar + t * 64;
            float4 v = make_float4(0.f, 0.f, 0.f, 0.f);
            if (m0 + row < N_NODES)
                v = *reinterpret_cast<const float4*>(x + (size_t)(m0 + row) * IN_CH + ck * BK + ac);
            uint4 u = make_uint4(f2tf32(v.x), f2tf32(v.y), f2tf32(v.z), f2tf32(v.w));
            *reinterpret_cast<uint4*>(&As[buf][row][ac]) = u;
        }
        #pragma unroll
        for (int t = 0; t < 2; t++) {
            int row = br + t * 8;
            float4 v = *reinterpret_cast<const float4*>(
                g_wcat + (size_t)(ck * BK + row) * OUTF + n0 + bc);
            uint4 u = make_uint4(f2tf32(v.x), f2tf32(v.y), f2tf32(v.z), f2tf32(v.w));
            *reinterpret_cast<uint4*>(&Bs[buf][row][bc]) = u;
        }
    };

    load_chunk(0, 0);
    __syncthreads();

    const int g  = lane >> 2;   // group id 0..7
    const int tg = lane & 3;    // thread in group 0..3

    for (int ck = 0; ck < NCK; ck++) {
        const int buf = ck & 1;
        #pragma unroll
        for (int ks = 0; ks < 2; ks++) {
            const int k0 = ks * 8;
            uint32_t a[2][4];
            #pragma unroll
            for (int mt = 0; mt < 2; mt++) {
                int r = wm * 32 + mt * 16 + g;
                a[mt][0] = As[buf][r][k0 + tg];
                a[mt][1] = As[buf][r + 8][k0 + tg];
                a[mt][2] = As[buf][r][k0 + tg + 4];
                a[mt][3] = As[buf][r + 8][k0 + tg + 4];
            }
            #pragma unroll
            for (int nt = 0; nt < 8; nt++) {
                int n = wn * 64 + nt * 8 + g;
                uint32_t b0 = Bs[buf][k0 + tg][n];
                uint32_t b1 = Bs[buf][k0 + tg + 4][n];
                mma_tf32(c[0][nt], a[0], b0, b1);
                mma_tf32(c[1][nt], a[1], b0, b1);
            }
        }
        if (ck + 1 < NCK) load_chunk(ck + 1, buf ^ 1);
        __syncthreads();
    }

    // epilogue: fp16 store + fused alpha dot products (exact fp32 accumulators)
    const int h = (n0 + wn * 64) >> 6;          // this warp's head
    #pragma unroll
    for (int mt = 0; mt < 2; mt++) {
        int r1 = wm * 32 + mt * 16 + g;
        int r2 = r1 + 8;
        int m1 = m0 + r1, m2 = m0 + r2;
        float s1 = 0.f, d1 = 0.f, s2 = 0.f, d2 = 0.f;
        #pragma unroll
        for (int nt = 0; nt < 8; nt++) {
            int n = n0 + wn * 64 + nt * 8 + tg * 2;
            float a0 = att_src[n], a1 = att_src[n + 1];
            float b0 = att_dst[n], b1 = att_dst[n + 1];
            s1 += c[mt][nt][0] * a0 + c[mt][nt][1] * a1;
            d1 += c[mt][nt][0] * b0 + c[mt][nt][1] * b1;
            s2 += c[mt][nt][2] * a0 + c[mt][nt][3] * a1;
            d2 += c[mt][nt][2] * b0 + c[mt][nt][3] * b1;
            if (m1 < N_NODES)
                *reinterpret_cast<__half2*>(g_xhh + (size_t)m1 * OUTF + n)
                    = __float22half2_rn(make_float2(c[mt][nt][0], c[mt][nt][1]));
            if (m2 < N_NODES)
                *reinterpret_cast<__half2*>(g_xhh + (size_t)m2 * OUTF + n)
                    = __float22half2_rn(make_float2(c[mt][nt][2], c[mt][nt][3]));
        }
        // reduce across the quad (tg = lane bits 0,1)
        s1 += __shfl_xor_sync(0xffffffffu, s1, 1); s1 += __shfl_xor_sync(0xffffffffu, s1, 2);
        d1 += __shfl_xor_sync(0xffffffffu, d1, 1); d1 += __shfl_xor_sync(0xffffffffu, d1, 2);
        s2 += __shfl_xor_sync(0xffffffffu, s2, 1); s2 += __shfl_xor_sync(0xffffffffu, s2, 2);
        d2 += __shfl_xor_sync(0xffffffffu, d2, 1); d2 += __shfl_xor_sync(0xffffffffu, d2, 2);
        if (tg == 0) {
            if (m1 < N_NODES) { g_asrc[m1 * 4 + h] = s1; g_adst[m1 * 4 + h] = d1; }
            if (m2 < N_NODES) { g_asrc[m2 * 4 + h] = s2; g_adst[m2 * 4 + h] = d2; }
        }
    }
}

// ---------------- histogram of destination rows ----------------
__global__ void k_hist(const int* __restrict__ ei) {
    int e = blockIdx.x * blockDim.x + threadIdx.x;
    if (e >= N_EDGES) return;
    atomicAdd(&g_cnt[clamp_idx(ei[e])], 1);
}

// ---------------- parallel scan, phase 1: per-block sums ----------------
__global__ void k_scan1() {
    __shared__ int wsum[32];
    int t = threadIdx.x;
    int i = blockIdx.x * 1024 + t;
    int v = (i < N_NODES) ? g_cnt[i] : 0;
    int lane = t & 31, wid = t >> 5;
    #pragma unroll
    for (int d = 16; d > 0; d >>= 1) v += __shfl_xor_sync(0xffffffffu, v, d);
    if (lane == 0) wsum[wid] = v;
    __syncthreads();
    if (wid == 0) {
        int s = wsum[lane];
        #pragma unroll
        for (int d = 16; d > 0; d >>= 1) s += __shfl_xor_sync(0xffffffffu, s, d);
        if (lane == 0) g_bsum[blockIdx.x] = s;
    }
}

// ---------------- phase 2: exclusive scan of block partials ----------------
__global__ void k_scan2(int nblk) {
    __shared__ int sm[64];
    int t = threadIdx.x;
    if (t < nblk) sm[t] = g_bsum[t];
    __syncthreads();
    if (t == 0) {
        int run = 0;
        for (int i = 0; i < nblk; i++) { int c = sm[i]; sm[i] = run; run += c; }
    }
    __syncthreads();
    if (t < nblk) g_bpre[t] = sm[t];
}

// ---------------- phase 3: block-local exclusive scan + prefix -> offsets ----------------
__global__ void k_scan3() {
    __shared__ int wsum[32];
    int t = threadIdx.x;
    int i = blockIdx.x * 1024 + t;
    int v = (i < N_NODES) ? g_cnt[i] : 0;
    int lane = t & 31, wid = t >> 5;
    int inc = v;
    #pragma unroll
    for (int d = 1; d < 32; d <<= 1) {
        int n = __shfl_up_sync(0xffffffffu, inc, d);
        if (lane >= d) inc += n;
    }
    if (lane == 31) wsum[wid] = inc;
    __syncthreads();
    if (wid == 0) {
        int s = wsum[lane];
        #pragma unroll
        for (int d = 1; d < 32; d <<= 1) {
            int n = __shfl_up_sync(0xffffffffu, s, d);
            if (lane >= d) s += n;
        }
        wsum[lane] = s;
    }
    __syncthreads();
    int ex = inc - v + ((wid > 0) ? wsum[wid - 1] : 0);
    int off = g_bpre[blockIdx.x] + ex;
    if (i < N_NODES) { g_off[i] = off; g_cur[i] = off; }
    if (blockIdx.x == 0 && t == 0) g_off[N_NODES] = N_EDGES;
}

// ---------------- fused edge pass: logits -> exp, reorder into CSR slots ----------------
__global__ void k_edge_fused(const int* __restrict__ ei) {
    int e = blockIdx.x * blockDim.x + threadIdx.x;
    if (e >= N_EDGES) return;
    int row = clamp_idx(ei[e]);
    int col = clamp_idx(ei[N_EDGES + e]);
    float4 s = *reinterpret_cast<const float4*>(g_asrc + row * 4);
    float4 d = *reinterpret_cast<const float4*>(g_adst + col * 4);
    float a0 = s.x + d.x, a1 = s.y + d.y, a2 = s.z + d.z, a3 = s.w + d.w;
    a0 = a0 > 0.f ? a0 : 0.2f * a0;
    a1 = a1 > 0.f ? a1 : 0.2f * a1;
    a2 = a2 > 0.f ? a2 : 0.2f * a2;
    a3 = a3 > 0.f ? a3 : 0.2f * a3;
    float4 p = make_float4(__expf(a0), __expf(a1), __expf(a2), __expf(a3));
    int pos = atomicAdd(&g_cur[row], 1);
    g_ecol[pos] = col;
    *reinterpret_cast<float4*>(g_eexp + (size_t)pos * 4) = p;
}

// ---------------- CSR gather: warp per node; lane owns 8 fp16 channels (one head) ----------------
__global__ void k_csr(const float* __restrict__ bias, float* __restrict__ out) {
    int warp = (blockIdx.x * blockDim.x + threadIdx.x) >> 5;
    if (warp >= N_NODES) return;
    int lane = threadIdx.x & 31;
    int n = warp;
    int off = g_off[n];
    int deg = g_off[n + 1] - off;
    const int head = lane >> 3;   // channels lane*8..lane*8+7 all in this head

    float acc[8];
    #pragma unroll
    for (int k = 0; k < 8; k++) acc[k] = 0.f;
    float den = 0.f;

    const uint4* xb = reinterpret_cast<const uint4*>(g_xhh);   // 8 fp16 per uint4, 32 per row

    for (int j = 0; j < deg; j++) {
        int idx = off + j;
        int c = g_ecol[idx];                                               // broadcast
        float4 p = *reinterpret_cast<const float4*>(g_eexp + (size_t)idx * 4); // broadcast
        float pa = (head == 0) ? p.x : (head == 1) ? p.y : (head == 2) ? p.z : p.w;
        den += pa;
        uint4 v = xb[(size_t)c * 32 + lane];
        float2 f0 = __half22float2(*reinterpret_cast<__half2*>(&v.x));
        float2 f1 = __half22float2(*reinterpret_cast<__half2*>(&v.y));
        float2 f2 = __half22float2(*reinterpret_cast<__half2*>(&v.z));
        float2 f3 = __half22float2(*reinterpret_cast<__half2*>(&v.w));
        acc[0] = fmaf(pa, f0.x, acc[0]); acc[1] = fmaf(pa, f0.y, acc[1]);
        acc[2] = fmaf(pa, f1.x, acc[2]); acc[3] = fmaf(pa, f1.y, acc[3]);
        acc[4] = fmaf(pa, f2.x, acc[4]); acc[5] = fmaf(pa, f2.y, acc[5]);
        acc[6] = fmaf(pa, f3.x, acc[6]); acc[7] = fmaf(pa, f3.y, acc[7]);
    }

    float r = 1.f / fmaxf(den, 1e-16f);
    const float4* b4 = reinterpret_cast<const float4*>(bias) + lane * 2;
    float4 b0 = b4[0], b1 = b4[1];
    float4 o0, o1;
    o0.x = fmaf(acc[0], r, b0.x); o0.y = fmaf(acc[1], r, b0.y);
    o0.z = fmaf(acc[2], r, b0.z); o0.w = fmaf(acc[3], r, b0.w);
    o1.x = fmaf(acc[4], r, b1.x); o1.y = fmaf(acc[5], r, b1.y);
    o1.z = fmaf(acc[6], r, b1.z); o1.w = fmaf(acc[7], r, b1.w);
    float4* dst = reinterpret_cast<float4*>(out) + (size_t)n * 64 + lane * 2;
    dst[0] = o0;
    dst[1] = o1;
}

// ---------------- launch ----------------
extern "C" void kernel_launch(void* const* d_in, const int* in_sizes, int n_in,
                              void* d_out, int out_size) {
    const float* x       = (const float*)d_in[0];
    const int*   ei      = (const int*)d_in[1];       // int32 (JAX x64 disabled)
    const float* w       = (const float*)d_in[2];
    const float* att_src = (const float*)d_in[3];
    const float* att_dst = (const float*)d_in[4];
    const float* bias    = (const float*)d_in[5];
    float*       out     = (float*)d_out;

    const int SCAN_BLOCKS = (N_NODES + 1023) / 1024;   // 49

    k_init<<<(N_NODES + 255) / 256, 256>>>();
    k_wrc<<<(HEADS * IN_CH * OUT_CH + 255) / 256, 256>>>(w);
    k_hist<<<(N_EDGES + 255) / 256, 256>>>(ei);
    k_scan1<<<SCAN_BLOCKS, 1024>>>();
    k_scan2<<<1, 64>>>(SCAN_BLOCKS);
    k_scan3<<<SCAN_BLOCKS, 1024>>>();

    dim3 gg((N_NODES + 127) / 128, OUTF / 128);
    k_gemm<<<gg, 256>>>(x, att_src, att_dst);

    k_edge_fused<<<(N_EDGES + 255) / 256, 256>>>(ei);
    k_csr<<<(N_NODES * 32 + 255) / 256, 256>>>(bias, out);
}